// round 6
// baseline (speedup 1.0000x reference)
#include <cuda_runtime.h>
#include <cstdint>

#define OH 7
#define OW 7
#define CC 8           // channels per block (== warps per block)
#define NROWS 14       // 2 corner rows per output row
#define NF4 17         // max float4 chunks per staged row
#define WPADF (NF4*4)  // 68 floats per staged row

__global__ void roialign_kernel(const float* __restrict__ feat,
                                const int* __restrict__ rois,
                                float* __restrict__ out,
                                int C, int H, int W) {
    __shared__ __align__(16) float s[CC * NROWS * WPADF];   // 30464 B

    const int n    = blockIdx.x;
    const int c0   = blockIdx.y * CC;
    const int tid  = threadIdx.x;
    const int warp = tid >> 5, lane = tid & 31;

    const int* r = rois + n * 5;
    const int b  = __ldg(r);
    const int x1 = __ldg(r + 1), y1 = __ldg(r + 2);
    const int x2 = __ldg(r + 3), y2 = __ldg(r + 4);

    const int xlo4 = x1 & ~3;
    const int xhi  = min(x2 + 1, W - 1);
    const int nf4  = min((xhi - xlo4 + 4) >> 2, (W - xlo4) >> 2);

    const float dy6 = (float)(y2 - y1) * 0.16666667f;
    const float dx6 = (float)(x2 - x1) * 0.16666667f;
    const float y1f = (float)y1, x1f = (float)x1;

    // per-lane staged-row offset: lanes 0..6 -> y0 rows, lanes 7..13 -> y1 rows
    // (sy in [y1,y2] subset [0,H-1] => trunc == floor, no lower/upper clamp on iy0)
    int myrowoff;
    {
        const int jj = (lane < 7) ? lane : lane - 7;
        float sy  = y1f + (float)jj * dy6;
        int   iy0 = (int)sy;
        int   iy1 = min(iy0 + 1, H - 1);
        myrowoff = ((lane < 7) ? iy0 : iy1) * W;
    }

    // ---- stage via cp.async: warp = channel, 16 lanes x 2 rows per step ----
    const float* gbase = feat + ((size_t)b * C + c0 + warp) * (size_t)(H * W) + xlo4;
    float* sbase = s + warp * (NROWS * WPADF);
    {
        const int i4   = lane & 15;
        const int rsel = lane >> 4;
        const bool needme = i4 < nf4;
        #pragma unroll
        for (int rp = 0; rp < 7; rp++) {
            const int row    = 2 * rp + rsel;
            const int rowoff = __shfl_sync(0xffffffffu, myrowoff, row);
            const float* src = gbase + rowoff + i4 * 4;
            const uint32_t dst =
                (uint32_t)__cvta_generic_to_shared(sbase + row * WPADF + i4 * 4);
            if (needme)
                asm volatile("cp.async.cg.shared.global [%0], [%1], 16;\n"
                             :: "r"(dst), "l"(src));
        }
        if (nf4 > 16) {  // rare 17th chunk
            const float* src = gbase + myrowoff + 64;
            const uint32_t dst =
                (uint32_t)__cvta_generic_to_shared(sbase + lane * WPADF + 64);
            if (lane < NROWS)
                asm volatile("cp.async.cg.shared.global [%0], [%1], 16;\n"
                             :: "r"(dst), "l"(src));
        }
        asm volatile("cp.async.commit_group;\n" ::: "memory");
        asm volatile("cp.async.wait_group 0;\n" ::: "memory");
        __syncwarp();
    }

    // ---- compute: 8-padded mapping, per-lane x-weights hoisted ----
    const int ox = lane & 7;                    // fixed across iterations
    float sx  = x1f + (float)ox * dx6;
    float x0f = floorf(sx);
    const float wx  = sx - x0f;
    const float omx = 1.0f - wx;
    int ix0 = (int)x0f;                         // in [x1, x2], no clamp needed
    int ix1 = min(ix0 + 1, W - 1);
    const int xa = ix0 - xlo4;
    const int xb = ix1 - xlo4;

    float* obase = out + ((size_t)(n * C + c0 + warp)) * (OH * OW);
    #pragma unroll
    for (int it = 0; it < 2; it++) {
        const int oy = (lane >> 3) + it * 4;
        if (ox < OW && oy < OH) {
            float sy  = y1f + (float)oy * dy6;
            float y0f = floorf(sy);
            const float wy  = sy - y0f;
            const float omy = 1.0f - wy;
            const float* p0 = sbase + oy * WPADF;
            const float* p1 = p0 + OH * WPADF;
            const float v00 = p0[xa], v01 = p0[xb];
            const float v10 = p1[xa], v11 = p1[xb];
            obase[oy * OW + ox] =
                (v00 * omx + v01 * wx) * omy + (v10 * omx + v11 * wx) * wy;
        }
    }
}

extern "C" void kernel_launch(void* const* d_in, const int* in_sizes, int n_in,
                              void* d_out, int out_size) {
    const float* feat = (const float*)d_in[0];
    const int*   rois = (const int*)d_in[1];
    float*       out  = (float*)d_out;

    const int C = 256, H = 200, W = 200;
    const int N = in_sizes[1] / 5;

    dim3 grid(N, C / CC);
    roialign_kernel<<<grid, 256>>>(feat, rois, out, C, H, W);
}